// round 12
// baseline (speedup 1.0000x reference)
#include <cuda_runtime.h>
#include <math.h>

#define N_ENTITY 64368
#define N_REL 40
#define DIM 128
#define N_BASES 8
#define N_EDGES 500000
#define BATCH 64
#define SEED_LEN 32

#define SCAN_BLK 1024
#define SCAN_NBLK 63            // 63*1024 = 64512 >= 64368
#define HIST_PAD (SCAN_NBLK * SCAN_BLK)

// ------------------------- device scratch (no allocs) ----------------------
// Zero-on-entry invariants, restored within the pipeline each call:
//   g_hist   : zeroed by scan (after reading)
//   g_total  : zeroed by hist (before scan runs)
//   g_deg    : zeroed by scan (before scatter accumulates)
//   g_agg    : zeroed by scatter (before agg accumulates)
//   g_cursor : zeroed by agg (after scatter used it)
__device__ float g_agg[(size_t)N_ENTITY * DIM];
__device__ float g_deg[N_ENTITY];
__device__ float g_u[BATCH * DIM];
__device__ int   g_hist[HIST_PAD];
__device__ int   g_cnt[HIST_PAD];      // persisted per-src count
__device__ int   g_start[HIST_PAD];    // group start
__device__ int   g_cursor[N_ENTITY];
__device__ int   g_total;
__device__ int   g_pack[N_EDGES];      // dst | (type<<20), grouped by src

// ---------------------------------------------------------------------------
// 1) histogram of src only (+ zero g_total for scan)
// ---------------------------------------------------------------------------
__global__ void hist_kernel(const int* __restrict__ src) {
    int e = blockIdx.x * blockDim.x + threadIdx.x;
    if (e == 0) g_total = 0;
    if (e >= N_EDGES) return;
    atomicAdd(&g_hist[src[e]], 1);
}

// ---------------------------------------------------------------------------
// 2) offset allocation: block scan + atomic block base. Persists count into
//    g_cnt, zeroes g_hist and g_deg.
// ---------------------------------------------------------------------------
__global__ void scan_kernel() {
    __shared__ int wsum[32];
    __shared__ int base_s;
    int t = threadIdx.x;
    int lane = t & 31, warp = t >> 5;
    int i = blockIdx.x * SCAN_BLK + t;
    int v = g_hist[i];
    g_hist[i] = 0;                       // restore invariant
    g_cnt[i] = v;
    if (i < N_ENTITY) g_deg[i] = 0.f;    // prepare for scatter's deg atomics

    int x = v;
#pragma unroll
    for (int o = 1; o < 32; o <<= 1) {
        int y = __shfl_up_sync(0xffffffffu, x, o);
        if (lane >= o) x += y;
    }
    if (lane == 31) wsum[warp] = x;
    __syncthreads();
    if (warp == 0) {
        int s = wsum[lane];
#pragma unroll
        for (int o = 1; o < 32; o <<= 1) {
            int y = __shfl_up_sync(0xffffffffu, s, o);
            if (lane >= o) s += y;
        }
        wsum[lane] = s;
    }
    __syncthreads();
    int incl = x + (warp ? wsum[warp - 1] : 0);
    if (t == SCAN_BLK - 1) base_s = atomicAdd(&g_total, incl);
    __syncthreads();
    g_start[i] = base_s + incl - v;
}

// ---------------------------------------------------------------------------
// 3) scatter edges grouped by src + deg accumulation + zero g_agg.
// ---------------------------------------------------------------------------
__global__ void scatter_kernel(const int* __restrict__ src,
                               const int* __restrict__ dst,
                               const int* __restrict__ typ) {
    int e = blockIdx.x * blockDim.x + threadIdx.x;
    int nthreads = gridDim.x * blockDim.x;

    size_t total4 = ((size_t)N_ENTITY * DIM) / 4;
    for (size_t i = e; i < total4; i += nthreads)
        ((float4*)g_agg)[i] = make_float4(0.f, 0.f, 0.f, 0.f);

    if (e >= N_EDGES) return;
    int s = src[e];
    int d = dst[e];
    int pos = g_start[s] + atomicAdd(&g_cursor[s], 1);
    g_pack[pos] = d | (typ[e] << 20);
    atomicAdd(&g_deg[d], 1.0f);
}

// ---------------------------------------------------------------------------
// 4) grouped aggregation (launch #4 -> ncu). R6 config: one warp per src,
//    flat launch, FFMA2 packed math, v4 RED. Also zeroes g_cursor.
// ---------------------------------------------------------------------------
#define FMA2(acc, c, v) \
    asm("fma.rn.f32x2 %0, %1, %2, %0;" : "+l"(acc) : "l"(c), "l"(v))

__global__ void __launch_bounds__(256)
agg_kernel(const float* __restrict__ basis, const float* __restrict__ att) {
    __shared__ __align__(16) unsigned long long att_dup[N_REL * N_BASES];
    int tid = threadIdx.x;
    for (int i = tid; i < N_REL * N_BASES; i += blockDim.x) {
        unsigned int ci = __float_as_uint(att[i]);
        att_dup[i] = ((unsigned long long)ci << 32) | (unsigned long long)ci;
    }
    __syncthreads();

    int w = (int)((blockIdx.x * blockDim.x + tid) >> 5);
    int lane = tid & 31;
    if (w >= N_ENTITY) return;
    int cnt = g_cnt[w];
    if (lane == 0) g_cursor[w] = 0;     // restore invariant
    if (cnt == 0) return;
    int start = g_start[w];

    unsigned long long r0[N_BASES], r1[N_BASES];
#pragma unroll
    for (int b = 0; b < N_BASES; b++) {
        ulonglong2 v = __ldg(
            (const ulonglong2*)(basis + ((size_t)b * N_ENTITY + (size_t)w) * DIM) + lane);
        r0[b] = v.x;
        r1[b] = v.y;
    }

    float* base_out = g_agg + (size_t)lane * 4;

    for (int i0 = 0; i0 < cnt; i0 += 32) {
        int n = min(32, cnt - i0);
        int pk = 0;
        if (lane < n) pk = g_pack[start + i0 + lane];
        for (int i = 0; i < n; i++) {
            int p = __shfl_sync(0xffffffffu, pk, i);
            int d = p & 0xFFFFF;
            int t = p >> 20;
            const ulonglong2* ad = (const ulonglong2*)(att_dup + t * N_BASES);
            ulonglong2 q0 = ad[0];
            ulonglong2 q1 = ad[1];
            ulonglong2 q2 = ad[2];
            ulonglong2 q3 = ad[3];

            unsigned long long acc0 = 0ull, acc1 = 0ull;
            FMA2(acc0, q0.x, r0[0]); FMA2(acc1, q0.x, r1[0]);
            FMA2(acc0, q0.y, r0[1]); FMA2(acc1, q0.y, r1[1]);
            FMA2(acc0, q1.x, r0[2]); FMA2(acc1, q1.x, r1[2]);
            FMA2(acc0, q1.y, r0[3]); FMA2(acc1, q1.y, r1[3]);
            FMA2(acc0, q2.x, r0[4]); FMA2(acc1, q2.x, r1[4]);
            FMA2(acc0, q2.y, r0[5]); FMA2(acc1, q2.y, r1[5]);
            FMA2(acc0, q3.x, r0[6]); FMA2(acc1, q3.x, r1[6]);
            FMA2(acc0, q3.y, r0[7]); FMA2(acc1, q3.y, r1[7]);

            float a0 = __uint_as_float((unsigned int)acc0);
            float a1 = __uint_as_float((unsigned int)(acc0 >> 32));
            float a2 = __uint_as_float((unsigned int)acc1);
            float a3 = __uint_as_float((unsigned int)(acc1 >> 32));

            float* outp = base_out + (size_t)d * DIM;
            asm volatile("red.global.add.v4.f32 [%0], {%1, %2, %3, %4};"
                         :: "l"(outp), "f"(a0), "f"(a1), "f"(a2), "f"(a3)
                         : "memory");
        }
    }
}

// ---------------------------------------------------------------------------
// 5) attention pooling (finalize fused into the gather)
// ---------------------------------------------------------------------------
__global__ void attn_kernel(const int* __restrict__ seed_ids,
                            const float* __restrict__ A,
                            const float* __restrict__ bvec,
                            const float* __restrict__ root,
                            const float* __restrict__ rbias) {
    __shared__ float H[SEED_LEN][DIM + 1];
    __shared__ float e_s[SEED_LEN];
    __shared__ float attnw[SEED_LEN];

    int b = blockIdx.x;
    int tid = threadIdx.x;
    int lane = tid & 31, warp = tid >> 5;

    for (int r = 0; r < SEED_LEN * DIM / 256; r++) {
        int idx = r * 256 + tid;
        int s = idx >> 7, d = idx & 127;
        int node = seed_ids[b * SEED_LEN + s];
        float invd = 1.0f / fmaxf(g_deg[node], 1.0f);
        H[s][d] = g_agg[(size_t)node * DIM + d] * invd +
                  __ldg(root + (size_t)node * DIM + d) + __ldg(rbias + d);
    }
    __syncthreads();

    float4 acc[4];
#pragma unroll
    for (int ss = 0; ss < 4; ss++) acc[ss] = make_float4(0.f, 0.f, 0.f, 0.f);
    int s0 = warp * 4;
#pragma unroll 4
    for (int k = 0; k < DIM; k++) {
        float4 a4 = __ldg((const float4*)(A + (size_t)k * DIM) + lane);
        float h0 = H[s0 + 0][k];
        float h1 = H[s0 + 1][k];
        float h2 = H[s0 + 2][k];
        float h3 = H[s0 + 3][k];
        acc[0].x = fmaf(h0, a4.x, acc[0].x); acc[0].y = fmaf(h0, a4.y, acc[0].y);
        acc[0].z = fmaf(h0, a4.z, acc[0].z); acc[0].w = fmaf(h0, a4.w, acc[0].w);
        acc[1].x = fmaf(h1, a4.x, acc[1].x); acc[1].y = fmaf(h1, a4.y, acc[1].y);
        acc[1].z = fmaf(h1, a4.z, acc[1].z); acc[1].w = fmaf(h1, a4.w, acc[1].w);
        acc[2].x = fmaf(h2, a4.x, acc[2].x); acc[2].y = fmaf(h2, a4.y, acc[2].y);
        acc[2].z = fmaf(h2, a4.z, acc[2].z); acc[2].w = fmaf(h2, a4.w, acc[2].w);
        acc[3].x = fmaf(h3, a4.x, acc[3].x); acc[3].y = fmaf(h3, a4.y, acc[3].y);
        acc[3].z = fmaf(h3, a4.z, acc[3].z); acc[3].w = fmaf(h3, a4.w, acc[3].w);
    }

    float4 b4 = __ldg((const float4*)bvec + lane);
#pragma unroll
    for (int ss = 0; ss < 4; ss++) {
        float v = tanhf(acc[ss].x) * b4.x + tanhf(acc[ss].y) * b4.y +
                  tanhf(acc[ss].z) * b4.z + tanhf(acc[ss].w) * b4.w;
#pragma unroll
        for (int o = 16; o > 0; o >>= 1) v += __shfl_xor_sync(0xffffffffu, v, o);
        if (lane == 0) e_s[s0 + ss] = v;
    }
    __syncthreads();

    if (warp == 0) {
        float ev = e_s[lane];
        float m = ev;
#pragma unroll
        for (int o = 16; o > 0; o >>= 1)
            m = fmaxf(m, __shfl_xor_sync(0xffffffffu, m, o));
        float ex = expf(ev - m);
        float ss2 = ex;
#pragma unroll
        for (int o = 16; o > 0; o >>= 1) ss2 += __shfl_xor_sync(0xffffffffu, ss2, o);
        attnw[lane] = ex / ss2;
    }
    __syncthreads();

    if (tid < DIM) {
        float u = 0.f;
#pragma unroll
        for (int s = 0; s < SEED_LEN; s++) u = fmaf(attnw[s], H[s][tid], u);
        g_u[b * DIM + tid] = u;
    }
}

// ---------------------------------------------------------------------------
// 6) scores: f32x2 FFMA2 GEMM, 8 ent x 8 batch per thread, transposed smem.
//    128 threads/block, ETILE=128 entities, KCH=32. Finalize fused in loader.
// ---------------------------------------------------------------------------
#define SC_THREADS 128
#define SC_ETILE 128
#define SC_KCH 32
__global__ void scores_kernel(const float* __restrict__ out_bias,
                              const float* __restrict__ root,
                              const float* __restrict__ rbias,
                              float* __restrict__ out) {
    __shared__ __align__(16) float nS[SC_KCH][SC_ETILE + 4];  // [k][entity]
    __shared__ __align__(16) float uS[SC_KCH][BATCH + 4];     // [k][batch]
    __shared__ float invd_s[SC_ETILE];

    int e0 = blockIdx.x * SC_ETILE;
    int tid = threadIdx.x;
    int eg = tid & 15;    // entity group: 8 entities each (16 groups * 8 = 128)
    int bg = tid >> 4;    // batch group:  8 batches  each (8 groups * 8 = 64)

    {
        int e = e0 + tid;   // SC_THREADS == SC_ETILE
        invd_s[tid] = (e < N_ENTITY) ? 1.0f / fmaxf(g_deg[e], 1.0f) : 0.f;
    }

    unsigned long long acc[4][8];   // [entity-pair][batch]
#pragma unroll
    for (int ep = 0; ep < 4; ep++)
#pragma unroll
        for (int j = 0; j < 8; j++) acc[ep][j] = 0ull;

    for (int kc = 0; kc < DIM; kc += SC_KCH) {
        __syncthreads();
        // nodes tile, transposed + finalize: nS[k][e]
        for (int q = tid; q < SC_ETILE * (SC_KCH / 4); q += SC_THREADS) {
            int e = q & (SC_ETILE - 1);
            int k4 = q >> 7;          // 0..7
            float4 nv = make_float4(0.f, 0.f, 0.f, 0.f);
            int ge = e0 + e;
            if (ge < N_ENTITY) {
                float4 a = *(const float4*)(g_agg + (size_t)ge * DIM + kc + k4 * 4);
                float4 rt = __ldg((const float4*)(root + (size_t)ge * DIM + kc + k4 * 4));
                float4 bb = __ldg((const float4*)(rbias + kc + k4 * 4));
                float iv = invd_s[e];
                nv.x = a.x * iv + rt.x + bb.x;
                nv.y = a.y * iv + rt.y + bb.y;
                nv.z = a.z * iv + rt.z + bb.z;
                nv.w = a.w * iv + rt.w + bb.w;
            }
            nS[k4 * 4 + 0][e] = nv.x;
            nS[k4 * 4 + 1][e] = nv.y;
            nS[k4 * 4 + 2][e] = nv.z;
            nS[k4 * 4 + 3][e] = nv.w;
        }
        // u tile, transposed: uS[k][b]
        for (int q = tid; q < BATCH * (SC_KCH / 4); q += SC_THREADS) {
            int b = q & (BATCH - 1);
            int k4 = q >> 6;          // 0..7
            float4 uv = *(const float4*)(g_u + b * DIM + kc + k4 * 4);
            uS[k4 * 4 + 0][b] = uv.x;
            uS[k4 * 4 + 1][b] = uv.y;
            uS[k4 * 4 + 2][b] = uv.z;
            uS[k4 * 4 + 3][b] = uv.w;
        }
        __syncthreads();

#pragma unroll 4
        for (int k = 0; k < SC_KCH; k++) {
            ulonglong2 n01 = *(const ulonglong2*)&nS[k][eg * 8];      // pairs (e0,e1),(e2,e3)
            ulonglong2 n23 = *(const ulonglong2*)&nS[k][eg * 8 + 4];  // pairs (e4,e5),(e6,e7)
#pragma unroll
            for (int j = 0; j < 8; j++) {
                float uf = uS[k][bg * 8 + j];
                unsigned long long ud;
                asm("mov.b64 %0, {%1, %1};" : "=l"(ud) : "r"(__float_as_uint(uf)));
                FMA2(acc[0][j], n01.x, ud);
                FMA2(acc[1][j], n01.y, ud);
                FMA2(acc[2][j], n23.x, ud);
                FMA2(acc[3][j], n23.y, ud);
            }
        }
    }

    // epilogue: unpack pairs, add bias, store
#pragma unroll
    for (int ep = 0; ep < 4; ep++) {
        int e = e0 + eg * 8 + ep * 2;
        if (e >= N_ENTITY) continue;
        bool has2 = (e + 1 < N_ENTITY);
        float ob0 = out_bias[e];
        float ob1 = has2 ? out_bias[e + 1] : 0.f;
#pragma unroll
        for (int j = 0; j < 8; j++) {
            int b = bg * 8 + j;
            float lo = __uint_as_float((unsigned int)acc[ep][j]);
            float hi = __uint_as_float((unsigned int)(acc[ep][j] >> 32));
            out[(size_t)b * N_ENTITY + e] = lo + ob0;
            if (has2) out[(size_t)b * N_ENTITY + e + 1] = hi + ob1;
        }
    }
}

// ---------------------------------------------------------------------------
extern "C" void kernel_launch(void* const* d_in, const int* in_sizes, int n_in,
                              void* d_out, int out_size) {
    const int*   seed_ids = (const int*)d_in[0];
    const int*   edge_src = (const int*)d_in[1];
    const int*   edge_dst = (const int*)d_in[2];
    const int*   edge_typ = (const int*)d_in[3];
    const float* basis    = (const float*)d_in[4];
    const float* att      = (const float*)d_in[5];
    const float* root     = (const float*)d_in[6];
    const float* rbias    = (const float*)d_in[7];
    const float* attn_a   = (const float*)d_in[8];
    const float* attn_b   = (const float*)d_in[9];
    const float* out_bias = (const float*)d_in[10];
    float* out = (float*)d_out;

    hist_kernel<<<(N_EDGES + 255) / 256, 256>>>(edge_src);                        // 1
    scan_kernel<<<SCAN_NBLK, SCAN_BLK>>>();                                       // 2
    scatter_kernel<<<(N_EDGES + 255) / 256, 256>>>(edge_src, edge_dst, edge_typ); // 3
    agg_kernel<<<(N_ENTITY * 32 + 255) / 256, 256>>>(basis, att);                 // 4 (ncu)
    attn_kernel<<<BATCH, 256>>>(seed_ids, attn_a, attn_b, root, rbias);           // 5
    {
        int blocks = (N_ENTITY + SC_ETILE - 1) / SC_ETILE;  // 503
        scores_kernel<<<blocks, SC_THREADS>>>(out_bias, root, rbias, out);        // 6
    }
}

// round 13
// speedup vs baseline: 1.0674x; 1.0674x over previous
#include <cuda_runtime.h>
#include <math.h>

#define N_ENTITY 64368
#define N_REL 40
#define DIM 128
#define N_BASES 8
#define N_EDGES 500000
#define BATCH 64
#define SEED_LEN 32

#define HIST_PAD 64512          // 252 * 256, >= N_ENTITY
#define PP_BLOCKS 222
#define PP_THREADS 256
#define PP_CHUNKS (HIST_PAD / 256)   // 252

// ------------------------- device scratch (no allocs) ----------------------
// Zero-on-entry invariants per call:
//   g_hist   : zeroed by prepass phase 2 (after reading)
//   g_cursor : zeroed by agg (after prepass phase 3 used it)
//   g_bar1/2 : zeroed by agg (after prepass completed)
//   g_agg, g_deg, g_total : zeroed by prepass phase 1
__device__ float g_agg[(size_t)N_ENTITY * DIM];
__device__ float g_deg[N_ENTITY];
__device__ float g_u[BATCH * DIM];
__device__ int   g_hist[HIST_PAD];
__device__ int   g_cnt[HIST_PAD];
__device__ int   g_start[HIST_PAD];
__device__ int   g_cursor[N_ENTITY];
__device__ int   g_total;
__device__ int   g_pack[N_EDGES];      // dst | (type<<20), grouped by src
__device__ int   g_bar1, g_bar2;       // persistent-kernel phase barriers

// ---------------------------------------------------------------------------
// software grid barrier (all PP_BLOCKS are co-resident: 222 blocks << capacity)
// ---------------------------------------------------------------------------
__device__ __forceinline__ void pp_barrier(int* bar) {
    __syncthreads();
    __threadfence();
    if (threadIdx.x == 0) {
        atomicAdd(bar, 1);
        while (atomicAdd(bar, 0) < PP_BLOCKS) __nanosleep(64);
    }
    __syncthreads();
}

// ---------------------------------------------------------------------------
// 1) persistent pre-pass: hist -> scan -> scatter, one kernel
// ---------------------------------------------------------------------------
__global__ void __launch_bounds__(PP_THREADS)
prepass_kernel(const int* __restrict__ src,
               const int* __restrict__ dst,
               const int* __restrict__ typ) {
    __shared__ int wsum[8];
    __shared__ int base_s;

    int tid = threadIdx.x;
    int gid = blockIdx.x * PP_THREADS + tid;
    const int NT = PP_BLOCKS * PP_THREADS;

    // ---- phase 1: histogram + zero g_agg / g_deg / g_total ----
    if (gid == 0) g_total = 0;
    for (int e = gid; e < N_EDGES; e += NT)
        atomicAdd(&g_hist[src[e]], 1);
    {
        size_t total4 = ((size_t)N_ENTITY * DIM) / 4;
        for (size_t i = gid; i < total4; i += NT)
            ((float4*)g_agg)[i] = make_float4(0.f, 0.f, 0.f, 0.f);
        for (int i = gid; i < N_ENTITY; i += NT)
            g_deg[i] = 0.f;
    }
    pp_barrier(&g_bar1);

    // ---- phase 2: per-256-chunk scan + atomic base (group order arbitrary) ----
    int lane = tid & 31, warp = tid >> 5;
    for (int c = blockIdx.x; c < PP_CHUNKS; c += PP_BLOCKS) {
        int i = c * 256 + tid;
        int v = g_hist[i];
        g_hist[i] = 0;               // restore invariant
        g_cnt[i] = v;

        int x = v;
#pragma unroll
        for (int o = 1; o < 32; o <<= 1) {
            int y = __shfl_up_sync(0xffffffffu, x, o);
            if (lane >= o) x += y;
        }
        if (lane == 31) wsum[warp] = x;
        __syncthreads();
        if (warp == 0 && lane < 8) {
            int s = wsum[lane];
#pragma unroll
            for (int o = 1; o < 8; o <<= 1) {
                int y = __shfl_up_sync(0xffu, s, o);
                if (lane >= o) s += y;
            }
            wsum[lane] = s;
        }
        __syncthreads();
        int incl = x + (warp ? wsum[warp - 1] : 0);
        if (tid == 255) base_s = atomicAdd(&g_total, incl);
        __syncthreads();
        g_start[i] = base_s + incl - v;
        __syncthreads();             // wsum/base_s reuse safety
    }
    pp_barrier(&g_bar2);

    // ---- phase 3: scatter + deg accumulation ----
    for (int e = gid; e < N_EDGES; e += NT) {
        int s = src[e];
        int d = dst[e];
        int pos = g_start[s] + atomicAdd(&g_cursor[s], 1);
        g_pack[pos] = d | (typ[e] << 20);
        atomicAdd(&g_deg[d], 1.0f);
    }
}

// ---------------------------------------------------------------------------
// 2) grouped aggregation (R6/R11 config: one warp per src, FFMA2, v4 RED).
//    Also zeroes g_cursor and the prepass barrier counters.
// ---------------------------------------------------------------------------
#define FMA2(acc, c, v) \
    asm("fma.rn.f32x2 %0, %1, %2, %0;" : "+l"(acc) : "l"(c), "l"(v))

__global__ void __launch_bounds__(256)
agg_kernel(const float* __restrict__ basis, const float* __restrict__ att) {
    __shared__ __align__(16) unsigned long long att_dup[N_REL * N_BASES];
    int tid = threadIdx.x;
    for (int i = tid; i < N_REL * N_BASES; i += blockDim.x) {
        unsigned int ci = __float_as_uint(att[i]);
        att_dup[i] = ((unsigned long long)ci << 32) | (unsigned long long)ci;
    }
    __syncthreads();

    if (blockIdx.x == 0 && tid == 0) { g_bar1 = 0; g_bar2 = 0; }  // restore

    int w = (int)((blockIdx.x * blockDim.x + tid) >> 5);
    int lane = tid & 31;
    if (w >= N_ENTITY) return;
    int cnt = g_cnt[w];
    if (lane == 0) g_cursor[w] = 0;     // restore invariant
    if (cnt == 0) return;
    int start = g_start[w];

    unsigned long long r0[N_BASES], r1[N_BASES];
#pragma unroll
    for (int b = 0; b < N_BASES; b++) {
        ulonglong2 v = __ldg(
            (const ulonglong2*)(basis + ((size_t)b * N_ENTITY + (size_t)w) * DIM) + lane);
        r0[b] = v.x;
        r1[b] = v.y;
    }

    float* base_out = g_agg + (size_t)lane * 4;

    for (int i0 = 0; i0 < cnt; i0 += 32) {
        int n = min(32, cnt - i0);
        int pk = 0;
        if (lane < n) pk = g_pack[start + i0 + lane];
        for (int i = 0; i < n; i++) {
            int p = __shfl_sync(0xffffffffu, pk, i);
            int d = p & 0xFFFFF;
            int t = p >> 20;
            const ulonglong2* ad = (const ulonglong2*)(att_dup + t * N_BASES);
            ulonglong2 q0 = ad[0];
            ulonglong2 q1 = ad[1];
            ulonglong2 q2 = ad[2];
            ulonglong2 q3 = ad[3];

            unsigned long long acc0 = 0ull, acc1 = 0ull;
            FMA2(acc0, q0.x, r0[0]); FMA2(acc1, q0.x, r1[0]);
            FMA2(acc0, q0.y, r0[1]); FMA2(acc1, q0.y, r1[1]);
            FMA2(acc0, q1.x, r0[2]); FMA2(acc1, q1.x, r1[2]);
            FMA2(acc0, q1.y, r0[3]); FMA2(acc1, q1.y, r1[3]);
            FMA2(acc0, q2.x, r0[4]); FMA2(acc1, q2.x, r1[4]);
            FMA2(acc0, q2.y, r0[5]); FMA2(acc1, q2.y, r1[5]);
            FMA2(acc0, q3.x, r0[6]); FMA2(acc1, q3.x, r1[6]);
            FMA2(acc0, q3.y, r0[7]); FMA2(acc1, q3.y, r1[7]);

            float a0 = __uint_as_float((unsigned int)acc0);
            float a1 = __uint_as_float((unsigned int)(acc0 >> 32));
            float a2 = __uint_as_float((unsigned int)acc1);
            float a3 = __uint_as_float((unsigned int)(acc1 >> 32));

            float* outp = base_out + (size_t)d * DIM;
            asm volatile("red.global.add.v4.f32 [%0], {%1, %2, %3, %4};"
                         :: "l"(outp), "f"(a0), "f"(a1), "f"(a2), "f"(a3)
                         : "memory");
        }
    }
}

// ---------------------------------------------------------------------------
// 3) attention pooling (finalize fused into the gather)
// ---------------------------------------------------------------------------
__global__ void attn_kernel(const int* __restrict__ seed_ids,
                            const float* __restrict__ A,
                            const float* __restrict__ bvec,
                            const float* __restrict__ root,
                            const float* __restrict__ rbias) {
    __shared__ float H[SEED_LEN][DIM + 1];
    __shared__ float e_s[SEED_LEN];
    __shared__ float attnw[SEED_LEN];

    int b = blockIdx.x;
    int tid = threadIdx.x;
    int lane = tid & 31, warp = tid >> 5;

    for (int r = 0; r < SEED_LEN * DIM / 256; r++) {
        int idx = r * 256 + tid;
        int s = idx >> 7, d = idx & 127;
        int node = seed_ids[b * SEED_LEN + s];
        float invd = 1.0f / fmaxf(g_deg[node], 1.0f);
        H[s][d] = g_agg[(size_t)node * DIM + d] * invd +
                  __ldg(root + (size_t)node * DIM + d) + __ldg(rbias + d);
    }
    __syncthreads();

    float4 acc[4];
#pragma unroll
    for (int ss = 0; ss < 4; ss++) acc[ss] = make_float4(0.f, 0.f, 0.f, 0.f);
    int s0 = warp * 4;
#pragma unroll 4
    for (int k = 0; k < DIM; k++) {
        float4 a4 = __ldg((const float4*)(A + (size_t)k * DIM) + lane);
        float h0 = H[s0 + 0][k];
        float h1 = H[s0 + 1][k];
        float h2 = H[s0 + 2][k];
        float h3 = H[s0 + 3][k];
        acc[0].x = fmaf(h0, a4.x, acc[0].x); acc[0].y = fmaf(h0, a4.y, acc[0].y);
        acc[0].z = fmaf(h0, a4.z, acc[0].z); acc[0].w = fmaf(h0, a4.w, acc[0].w);
        acc[1].x = fmaf(h1, a4.x, acc[1].x); acc[1].y = fmaf(h1, a4.y, acc[1].y);
        acc[1].z = fmaf(h1, a4.z, acc[1].z); acc[1].w = fmaf(h1, a4.w, acc[1].w);
        acc[2].x = fmaf(h2, a4.x, acc[2].x); acc[2].y = fmaf(h2, a4.y, acc[2].y);
        acc[2].z = fmaf(h2, a4.z, acc[2].z); acc[2].w = fmaf(h2, a4.w, acc[2].w);
        acc[3].x = fmaf(h3, a4.x, acc[3].x); acc[3].y = fmaf(h3, a4.y, acc[3].y);
        acc[3].z = fmaf(h3, a4.z, acc[3].z); acc[3].w = fmaf(h3, a4.w, acc[3].w);
    }

    float4 b4 = __ldg((const float4*)bvec + lane);
#pragma unroll
    for (int ss = 0; ss < 4; ss++) {
        float v = tanhf(acc[ss].x) * b4.x + tanhf(acc[ss].y) * b4.y +
                  tanhf(acc[ss].z) * b4.z + tanhf(acc[ss].w) * b4.w;
#pragma unroll
        for (int o = 16; o > 0; o >>= 1) v += __shfl_xor_sync(0xffffffffu, v, o);
        if (lane == 0) e_s[s0 + ss] = v;
    }
    __syncthreads();

    if (warp == 0) {
        float ev = e_s[lane];
        float m = ev;
#pragma unroll
        for (int o = 16; o > 0; o >>= 1)
            m = fmaxf(m, __shfl_xor_sync(0xffffffffu, m, o));
        float ex = expf(ev - m);
        float ss2 = ex;
#pragma unroll
        for (int o = 16; o > 0; o >>= 1) ss2 += __shfl_xor_sync(0xffffffffu, ss2, o);
        attnw[lane] = ex / ss2;
    }
    __syncthreads();

    if (tid < DIM) {
        float u = 0.f;
#pragma unroll
        for (int s = 0; s < SEED_LEN; s++) u = fmaf(attnw[s], H[s][tid], u);
        g_u[b * DIM + tid] = u;
    }
}

// ---------------------------------------------------------------------------
// 4) scores (launch #4 -> ncu target). EXACT R11 version (known good).
// ---------------------------------------------------------------------------
#define ETILE 64
#define KCH 64
__global__ void scores_kernel(const float* __restrict__ out_bias,
                              const float* __restrict__ root,
                              const float* __restrict__ rbias,
                              float* __restrict__ out) {
    __shared__ float nS[ETILE][KCH + 1];
    __shared__ float uS[BATCH][KCH + 1];
    __shared__ float invd_s[ETILE];
    int e0 = blockIdx.x * ETILE;
    int tid = threadIdx.x;
    int ti = tid & 15;
    int tj = tid >> 4;

    if (tid < ETILE) {
        int e = e0 + tid;
        invd_s[tid] = (e < N_ENTITY) ? 1.0f / fmaxf(g_deg[e], 1.0f) : 0.f;
    }

    float acc[4][4];
#pragma unroll
    for (int i = 0; i < 4; i++)
#pragma unroll
        for (int j = 0; j < 4; j++) acc[i][j] = 0.f;

    for (int kc = 0; kc < DIM; kc += KCH) {
        __syncthreads();
        for (int q = tid; q < ETILE * (KCH / 4); q += 256) {
            int r = q >> 4;
            int c4 = (q & 15) * 4;
            int e = e0 + r;
            float4 nv = make_float4(0.f, 0.f, 0.f, 0.f);
            if (e < N_ENTITY) {
                float4 a = *(const float4*)(g_agg + (size_t)e * DIM + kc + c4);
                float4 rt = __ldg((const float4*)(root + (size_t)e * DIM + kc + c4));
                float4 bb = __ldg((const float4*)(rbias + kc + c4));
                float iv = invd_s[r];
                nv.x = a.x * iv + rt.x + bb.x;
                nv.y = a.y * iv + rt.y + bb.y;
                nv.z = a.z * iv + rt.z + bb.z;
                nv.w = a.w * iv + rt.w + bb.w;
            }
            nS[r][c4 + 0] = nv.x; nS[r][c4 + 1] = nv.y;
            nS[r][c4 + 2] = nv.z; nS[r][c4 + 3] = nv.w;
            float4 uv = *(const float4*)(g_u + r * DIM + kc + c4);
            uS[r][c4 + 0] = uv.x; uS[r][c4 + 1] = uv.y;
            uS[r][c4 + 2] = uv.z; uS[r][c4 + 3] = uv.w;
        }
        __syncthreads();
#pragma unroll 8
        for (int k = 0; k < KCH; k++) {
            float nf[4], uf[4];
#pragma unroll
            for (int i = 0; i < 4; i++) nf[i] = nS[ti * 4 + i][k];
#pragma unroll
            for (int j = 0; j < 4; j++) uf[j] = uS[tj * 4 + j][k];
#pragma unroll
            for (int i = 0; i < 4; i++)
#pragma unroll
                for (int j = 0; j < 4; j++)
                    acc[i][j] = fmaf(nf[i], uf[j], acc[i][j]);
        }
    }

#pragma unroll
    for (int i = 0; i < 4; i++) {
        int e = e0 + ti * 4 + i;
        if (e >= N_ENTITY) continue;
        float ob = out_bias[e];
#pragma unroll
        for (int j = 0; j < 4; j++) {
            int bb = tj * 4 + j;
            out[(size_t)bb * N_ENTITY + e] = acc[i][j] + ob;
        }
    }
}

// ---------------------------------------------------------------------------
extern "C" void kernel_launch(void* const* d_in, const int* in_sizes, int n_in,
                              void* d_out, int out_size) {
    const int*   seed_ids = (const int*)d_in[0];
    const int*   edge_src = (const int*)d_in[1];
    const int*   edge_dst = (const int*)d_in[2];
    const int*   edge_typ = (const int*)d_in[3];
    const float* basis    = (const float*)d_in[4];
    const float* att      = (const float*)d_in[5];
    const float* root     = (const float*)d_in[6];
    const float* rbias    = (const float*)d_in[7];
    const float* attn_a   = (const float*)d_in[8];
    const float* attn_b   = (const float*)d_in[9];
    const float* out_bias = (const float*)d_in[10];
    float* out = (float*)d_out;

    prepass_kernel<<<PP_BLOCKS, PP_THREADS>>>(edge_src, edge_dst, edge_typ);  // 1
    agg_kernel<<<(N_ENTITY * 32 + 255) / 256, 256>>>(basis, att);             // 2
    attn_kernel<<<BATCH, 256>>>(seed_ids, attn_a, attn_b, root, rbias);       // 3
    scores_kernel<<<(N_ENTITY + ETILE - 1) / ETILE, 256>>>(out_bias, root, rbias, out); // 4 (ncu)
}